// round 10
// baseline (speedup 1.0000x reference)
#include <cuda_runtime.h>
#include <cuda_bf16.h>
#include <cstdint>

#define B_ 16
#define T_ 2048
#define L_ 128
#define H_ 512
#define M_IN 256
#define F_ 1024
#define LP 130                 // U table row-block: 128 ch + 1 const + 1 pad
#define C_CHUNK 16
#define Q_CHUNK 16
#define KX 2048                // X k-width: 16 * 128 (no const row)
#define MZ (Q_CHUNK * B_)      // 256
#define NSPLIT 8
#define KPER 256
#define SCAN_BLOCKS 64

typedef __nv_bfloat16 bf16;

__device__ __align__(16) bf16 g_A0h[H_ * H_], g_A0l[H_ * H_];
__device__ __align__(16) bf16 g_Uh[C_CHUNK * LP * H_], g_Ul[C_CHUNK * LP * H_];
__device__ __align__(16) bf16 g_Ph[4 * H_ * H_], g_Pl[4 * H_ * H_];
__device__ __align__(16) bf16 g_Xh[MZ * KX], g_Xl[MZ * KX];
__device__ __align__(16) float g_Gf[H_ * H_];
__device__ __align__(16) float g_Zp[NSPLIT * MZ * H_];
__device__ __align__(16) float g_S0[B_ * H_], g_S1[B_ * H_];
__device__ int g_cnt;
__device__ int g_gen;

__device__ __forceinline__ void splitw(float v, bf16* ph, bf16* pl) {
    bf16 h = __float2bfloat16(v);
    *ph = h;
    *pl = __float2bfloat16(v - __bfloat162float(h));
}

// ------------------------- merged prep kernel ------------------------------
// blocks [0,1024): splitA; [1024,1284): initW0; [1284,3332): gather X
__global__ void k_prep(const float* __restrict__ A, const float* __restrict__ We,
                       const float* __restrict__ be, const float* __restrict__ Wb,
                       const float* __restrict__ x) {
    const int NB_A = (H_ * H_) / 256;          // 1024
    const int NB_W = (LP * H_ + 255) / 256;    // 260
    int bid = blockIdx.x, tid = threadIdx.x;
    if (bid == 0 && tid == 0) { g_cnt = 0; g_gen = 0; }
    if (bid < NB_A) {
        int i = bid * 256 + tid;
        splitw(A[i], &g_A0h[i], &g_A0l[i]);
    } else if (bid < NB_A + NB_W) {
        int i = (bid - NB_A) * 256 + tid;
        if (i >= LP * H_) return;
        int l = i >> 9, h = i & 511;
        float acc = 0.f;
        if (l < 128) { for (int m = 0; m < M_IN; m++) acc += We[l * M_IN + m] * Wb[m * H_ + h]; }
        else if (l == 128) { for (int m = 0; m < M_IN; m++) acc += be[m] * Wb[m * H_ + h]; }
        splitw(acc, &g_Uh[i], &g_Ul[i]);
    } else {
        int i = (bid - NB_A - NB_W) * 256 + tid;   // < MZ*KX = 524288
        int m = i >> 11, kk = i & 2047;
        int r = kk >> 7, l = kk & 127;
        int q = m >> 4, b = m & 15;
        float v = x[((size_t)b * T_ + (T_ - 1) - (q * C_CHUNK + r)) * L_ + l];
        splitw(v, &g_Xh[i], &g_Xl[i]);
    }
}

// ---------------------------------------------------------------------------
__device__ __forceinline__ void ldsm4(uint32_t* r, const void* p) {
    uint32_t addr = (uint32_t)__cvta_generic_to_shared(p);
    asm volatile("ldmatrix.sync.aligned.m8n8.x4.shared.b16 {%0,%1,%2,%3}, [%4];"
                 : "=r"(r[0]), "=r"(r[1]), "=r"(r[2]), "=r"(r[3]) : "r"(addr));
}
__device__ __forceinline__ void ldsm4t(uint32_t* r, const void* p) {
    uint32_t addr = (uint32_t)__cvta_generic_to_shared(p);
    asm volatile("ldmatrix.sync.aligned.m8n8.x4.trans.shared.b16 {%0,%1,%2,%3}, [%4];"
                 : "=r"(r[0]), "=r"(r[1]), "=r"(r[2]), "=r"(r[3]) : "r"(addr));
}
__device__ __forceinline__ void mma16816(float* d, const uint32_t* a, const uint32_t* b) {
    asm volatile("mma.sync.aligned.m16n8k16.row.col.f32.bf16.bf16.f32 "
                 "{%0,%1,%2,%3}, {%4,%5,%6,%7}, {%8,%9}, {%0,%1,%2,%3};"
                 : "+f"(d[0]), "+f"(d[1]), "+f"(d[2]), "+f"(d[3])
                 : "r"(a[0]), "r"(a[1]), "r"(a[2]), "r"(a[3]), "r"(b[0]), "r"(b[1]));
}

// C[M x 512] = A[M x K] @ B[K x 512], all operands bf16 hi/lo pairs.
// 64x64 tiles, 256 threads. Double-buffered smem + register prefetch:
// one __syncthreads per k-iteration; global loads overlap the mma burst.
__global__ __launch_bounds__(256) void k_tgemm(
    const bf16* __restrict__ A1h, const bf16* __restrict__ A1l,
    const bf16* __restrict__ A2h, const bf16* __restrict__ A2l,
    int Mu, int Mtot, int lda,
    const bf16* __restrict__ Bhg, const bf16* __restrict__ Blg,
    bf16* C1h, bf16* C1l, bf16* C2h, bf16* C2l,
    float* C1f, float* C2f,
    int kper, int K)
{
    __shared__ __align__(16) bf16 Ash[2][64][40];
    __shared__ __align__(16) bf16 Asl[2][64][40];
    __shared__ __align__(16) bf16 Bsh[2][32][72];
    __shared__ __align__(16) bf16 Bsl[2][32][72];

    int tid = threadIdx.x;
    int lane = tid & 31, wid = tid >> 5;
    int wm = wid & 1, wn = wid >> 1;
    int row0 = blockIdx.y * 64, col0 = blockIdx.x * 64;
    int k0 = blockIdx.z * kper, k1 = k0 + kper; if (k1 > K) k1 = K;
    size_t coff = (size_t)blockIdx.z * Mtot * H_;

    float acc[2][2][4];
    #pragma unroll
    for (int a = 0; a < 2; a++)
        #pragma unroll
        for (int b = 0; b < 2; b++)
            #pragma unroll
            for (int c = 0; c < 4; c++) acc[a][b][c] = 0.f;

    int a_r = (lane & 7) + (lane & 8);
    int a_c = (lane & 16) ? 8 : 0;
    int b_r = (lane & 7) + (lane & 8);
    int b_c = (lane & 16) ? 8 : 0;

    int am = tid >> 2, ac8 = (tid & 3) * 8;
    int sbk = tid >> 3, sbn = (tid & 7) * 8;

    int ar_g = row0 + am;
    bool a_ok = (ar_g < Mtot);
    bool a_lo = a_ok && (ar_g < Mu);
    const bf16* ash_src = a_ok ? ((a_lo ? A1h : A2h) + (size_t)(a_lo ? ar_g : ar_g - Mu) * lda + ac8) : nullptr;
    const bf16* asl_src = a_ok ? ((a_lo ? A1l : A2l) + (size_t)(a_lo ? ar_g : ar_g - Mu) * lda + ac8) : nullptr;
    const bf16* bsh_src = Bhg + (size_t)sbk * H_ + col0 + sbn;
    const bf16* bsl_src = Blg + (size_t)sbk * H_ + col0 + sbn;

    uint4 pAh = make_uint4(0,0,0,0), pAl = pAh, pBh, pBl;
    // prologue
    if (a_ok) { pAh = *(const uint4*)(ash_src + k0); pAl = *(const uint4*)(asl_src + k0); }
    pBh = *(const uint4*)(bsh_src + (size_t)k0 * H_);
    pBl = *(const uint4*)(bsl_src + (size_t)k0 * H_);

    int iters = (k1 - k0) >> 5;
    int st = 0;
    for (int it = 0; it < iters; it++) {
        *(uint4*)&Ash[st][am][ac8] = pAh;
        *(uint4*)&Asl[st][am][ac8] = pAl;
        *(uint4*)&Bsh[st][sbk][sbn] = pBh;
        *(uint4*)&Bsl[st][sbk][sbn] = pBl;
        __syncthreads();

        if (it + 1 < iters) {
            int kn = k0 + ((it + 1) << 5);
            if (a_ok) { pAh = *(const uint4*)(ash_src + kn); pAl = *(const uint4*)(asl_src + kn); }
            pBh = *(const uint4*)(bsh_src + (size_t)kn * H_);
            pBl = *(const uint4*)(bsl_src + (size_t)kn * H_);
        }

        #pragma unroll
        for (int ks = 0; ks < 2; ks++) {
            int kc = ks * 16;
            uint32_t ah[2][4], al[2][4], bh[4], bl[4];
            #pragma unroll
            for (int mt = 0; mt < 2; mt++) {
                int mr = wm * 32 + mt * 16 + a_r;
                ldsm4(ah[mt], &Ash[st][mr][kc + a_c]);
                ldsm4(al[mt], &Asl[st][mr][kc + a_c]);
            }
            {
                int nb = wn * 16 + b_c;
                ldsm4t(bh, &Bsh[st][kc + b_r][nb]);
                ldsm4t(bl, &Bsl[st][kc + b_r][nb]);
            }
            #pragma unroll
            for (int mt = 0; mt < 2; mt++)
                #pragma unroll
                for (int nt = 0; nt < 2; nt++) {
                    const uint32_t* bhf = &bh[nt * 2];
                    const uint32_t* blf = &bl[nt * 2];
                    mma16816(acc[mt][nt], ah[mt], bhf);
                    mma16816(acc[mt][nt], ah[mt], blf);
                    mma16816(acc[mt][nt], al[mt], bhf);
                }
        }
        st ^= 1;
    }

    #pragma unroll
    for (int mt = 0; mt < 2; mt++)
        #pragma unroll
        for (int nt = 0; nt < 2; nt++) {
            int c = col0 + wn * 16 + nt * 8 + (lane & 3) * 2;
            #pragma unroll
            for (int half = 0; half < 2; half++) {
                int r = row0 + wm * 32 + mt * 16 + (lane >> 2) + half * 8;
                if (r >= Mtot) continue;
                float v0 = acc[mt][nt][half * 2], v1 = acc[mt][nt][half * 2 + 1];
                bool lo = (r < Mu);
                size_t ro = lo ? (size_t)r * H_ : (size_t)(r - Mu) * H_;
                bf16* ch = lo ? C1h : C2h;
                bf16* cl = lo ? C1l : C2l;
                float* cf = lo ? C1f : C2f;
                if (ch) {
                    splitw(v0, &ch[coff + ro + c], &cl[coff + ro + c]);
                    splitw(v1, &ch[coff + ro + c + 1], &cl[coff + ro + c + 1]);
                }
                if (cf) { cf[coff + ro + c] = v0; cf[coff + ro + c + 1] = v1; }
            }
        }
}

// Z = X[256 x 2048] @ U' where U' row k = U row (k>>7)*130 + (k&127).
// Same pipelined structure. split-K slice z covers [z*256, z*256+256).
__global__ __launch_bounds__(256) void k_zgemm() {
    __shared__ __align__(16) bf16 Ash[2][64][40];
    __shared__ __align__(16) bf16 Asl[2][64][40];
    __shared__ __align__(16) bf16 Bsh[2][32][72];
    __shared__ __align__(16) bf16 Bsl[2][32][72];

    int tid = threadIdx.x;
    int lane = tid & 31, wid = tid >> 5;
    int wm = wid & 1, wn = wid >> 1;
    int row0 = blockIdx.y * 64, col0 = blockIdx.x * 64;
    int k0 = blockIdx.z * KPER;
    size_t coff = (size_t)blockIdx.z * MZ * H_;

    float acc[2][2][4];
    #pragma unroll
    for (int a = 0; a < 2; a++)
        #pragma unroll
        for (int b = 0; b < 2; b++)
            #pragma unroll
            for (int c = 0; c < 4; c++) acc[a][b][c] = 0.f;

    int a_r = (lane & 7) + (lane & 8);
    int a_c = (lane & 16) ? 8 : 0;
    int b_r = (lane & 7) + (lane & 8);
    int b_c = (lane & 16) ? 8 : 0;

    int am = tid >> 2, ac8 = (tid & 3) * 8;
    int sbk = tid >> 3, sbn = (tid & 7) * 8;

    const bf16* ash_src = g_Xh + (size_t)(row0 + am) * KX + ac8;
    const bf16* asl_src = g_Xl + (size_t)(row0 + am) * KX + ac8;

    uint4 pAh, pAl, pBh, pBl;
    {
        pAh = *(const uint4*)(ash_src + k0);
        pAl = *(const uint4*)(asl_src + k0);
        int kg = k0 + sbk;
        size_t brow = (size_t)((kg >> 7) * LP + (kg & 127)) * H_ + col0 + sbn;
        pBh = *(const uint4*)(g_Uh + brow);
        pBl = *(const uint4*)(g_Ul + brow);
    }

    const int iters = KPER >> 5;
    int st = 0;
    for (int it = 0; it < iters; it++) {
        *(uint4*)&Ash[st][am][ac8] = pAh;
        *(uint4*)&Asl[st][am][ac8] = pAl;
        *(uint4*)&Bsh[st][sbk][sbn] = pBh;
        *(uint4*)&Bsl[st][sbk][sbn] = pBl;
        __syncthreads();

        if (it + 1 < iters) {
            int kn = k0 + ((it + 1) << 5);
            pAh = *(const uint4*)(ash_src + kn);
            pAl = *(const uint4*)(asl_src + kn);
            int kg = kn + sbk;
            size_t brow = (size_t)((kg >> 7) * LP + (kg & 127)) * H_ + col0 + sbn;
            pBh = *(const uint4*)(g_Uh + brow);
            pBl = *(const uint4*)(g_Ul + brow);
        }

        #pragma unroll
        for (int ks = 0; ks < 2; ks++) {
            int kc = ks * 16;
            uint32_t ah[2][4], al[2][4], bh[4], bl[4];
            #pragma unroll
            for (int mt = 0; mt < 2; mt++) {
                int mr = wm * 32 + mt * 16 + a_r;
                ldsm4(ah[mt], &Ash[st][mr][kc + a_c]);
                ldsm4(al[mt], &Asl[st][mr][kc + a_c]);
            }
            {
                int nb = wn * 16 + b_c;
                ldsm4t(bh, &Bsh[st][kc + b_r][nb]);
                ldsm4t(bl, &Bsl[st][kc + b_r][nb]);
            }
            #pragma unroll
            for (int mt = 0; mt < 2; mt++)
                #pragma unroll
                for (int nt = 0; nt < 2; nt++) {
                    const uint32_t* bhf = &bh[nt * 2];
                    const uint32_t* blf = &bl[nt * 2];
                    mma16816(acc[mt][nt], ah[mt], bhf);
                    mma16816(acc[mt][nt], ah[mt], blf);
                    mma16816(acc[mt][nt], al[mt], bhf);
                }
        }
        st ^= 1;
    }

    #pragma unroll
    for (int mt = 0; mt < 2; mt++)
        #pragma unroll
        for (int nt = 0; nt < 2; nt++) {
            int c = col0 + wn * 16 + nt * 8 + (lane & 3) * 2;
            #pragma unroll
            for (int half = 0; half < 2; half++) {
                int r = row0 + wm * 32 + mt * 16 + (lane >> 2) + half * 8;
                float* cp = g_Zp + coff + (size_t)r * H_ + c;
                cp[0] = acc[mt][nt][half * 2];
                cp[1] = acc[mt][nt][half * 2 + 1];
            }
        }
}

// ---------------------------------------------------------------------------
__device__ __forceinline__ void gridbar(int it) {
    __syncthreads();
    __threadfence();
    if (threadIdx.x == 0) {
        int t = atomicAdd(&g_cnt, 1);
        if (t == SCAN_BLOCKS - 1) {
            atomicExch(&g_cnt, 0);
            __threadfence();
            atomicAdd(&g_gen, 1);
        }
        while (*(volatile int*)&g_gen < it + 1) {}
    }
    __syncthreads();
}

// Horner scan: S = Z_15+bias; for q=14..0: S = S@G + Z_q + bias  (G = A^16).
// bias[h] = sum_{r<16} U[r*130+128][h]
__global__ __launch_bounds__(256) void k_scanall() {
    __shared__ float Ssm[4][H_];
    __shared__ float red[32][128];
    __shared__ float bias[32];
    int tid = threadIdx.x;
    int bg = blockIdx.x >> 4;
    int hg = blockIdx.x & 15;
    int krep = tid >> 3;
    int hslot = tid & 7;
    int h = hg * 32 + hslot * 4;
    const float* gp = g_Gf + (size_t)(krep * 16) * H_ + h;

    if (tid < 32) {
        int hc = hg * 32 + tid;
        float s = 0.f;
        #pragma unroll
        for (int r = 0; r < C_CHUNK; r++) {
            size_t off = (size_t)(r * LP + 128) * H_ + hc;
            s += __bfloat162float(g_Uh[off]) + __bfloat162float(g_Ul[off]);
        }
        bias[tid] = s;
    }
    __syncthreads();

    for (int i = 0; i < 16; i++) {
        int q = 15 - i;
        float a0[4] = {}, a1[4] = {}, a2[4] = {}, a3[4] = {};
        if (i > 0) {
            const float* Sin = ((i - 1) & 1) ? g_S1 : g_S0;
            for (int t = tid; t < 4 * H_; t += 256)
                Ssm[t >> 9][t & 511] = Sin[(bg * 4 + (t >> 9)) * H_ + (t & 511)];
            __syncthreads();
            #pragma unroll 4
            for (int kk = 0; kk < 16; kk++) {
                int k = (kk + krep) & 15;
                float4 g = *(const float4*)(gp + (size_t)k * H_);
                float s0 = Ssm[0][krep * 16 + k];
                float s1 = Ssm[1][krep * 16 + k];
                float s2 = Ssm[2][krep * 16 + k];
                float s3 = Ssm[3][krep * 16 + k];
                a0[0] += s0 * g.x; a0[1] += s0 * g.y; a0[2] += s0 * g.z; a0[3] += s0 * g.w;
                a1[0] += s1 * g.x; a1[1] += s1 * g.y; a1[2] += s1 * g.z; a1[3] += s1 * g.w;
                a2[0] += s2 * g.x; a2[1] += s2 * g.y; a2[2] += s2 * g.z; a2[3] += s2 * g.w;
                a3[0] += s3 * g.x; a3[1] += s3 * g.y; a3[2] += s3 * g.z; a3[3] += s3 * g.w;
            }
        }
        *(float4*)&red[krep][0 * 32 + hslot * 4] = *(float4*)a0;
        *(float4*)&red[krep][1 * 32 + hslot * 4] = *(float4*)a1;
        *(float4*)&red[krep][2 * 32 + hslot * 4] = *(float4*)a2;
        *(float4*)&red[krep][3 * 32 + hslot * 4] = *(float4*)a3;
        __syncthreads();
        if (tid < 128) {
            float v = 0.f;
            #pragma unroll
            for (int s = 0; s < 32; s++) v += red[s][tid];
            int b = tid >> 5, hcl = tid & 31;
            int m = q * 16 + bg * 4 + b;
            int hc = hg * 32 + hcl;
            float z = bias[hcl];
            #pragma unroll
            for (int s2 = 0; s2 < NSPLIT; s2++)
                z += g_Zp[(size_t)s2 * (MZ * H_) + (size_t)m * H_ + hc];
            float* Sout = (i & 1) ? g_S1 : g_S0;
            Sout[(bg * 4 + b) * H_ + hc] = v + z;
        }
        if (i < 15) gridbar(i);
    }
}

// ---------------------------------------------------------------------------
__global__ void k_final(const float* __restrict__ S, const float* __restrict__ x,
                        const float* __restrict__ Wr, const float* __restrict__ br,
                        const float* __restrict__ lng, const float* __restrict__ lnb,
                        const float* __restrict__ W1, const float* __restrict__ b1,
                        const float* __restrict__ W2, const float* __restrict__ b2,
                        float* __restrict__ out) {
    int b = blockIdx.x, tid = threadIdx.x;
    __shared__ float xs[L_], z[H_], a[F_], r1[8], r2[8];
    __shared__ float mu_s, rs_s;
    if (tid < L_) xs[tid] = x[((size_t)b * T_ + (T_ - 1)) * L_ + tid];
    __syncthreads();
    for (int h = tid; h < H_; h += 256) {
        float acc = S[b * H_ + h] + br[h];
        for (int l = 0; l < L_; l++) acc += xs[l] * Wr[(size_t)l * H_ + h];
        z[h] = acc;
    }
    __syncthreads();
    float s1 = 0.f, s2 = 0.f;
    for (int h = tid; h < H_; h += 256) { float v = z[h]; s1 += v; s2 += v * v; }
    #pragma unroll
    for (int o = 16; o; o >>= 1) {
        s1 += __shfl_xor_sync(0xFFFFFFFFu, s1, o);
        s2 += __shfl_xor_sync(0xFFFFFFFFu, s2, o);
    }
    if ((tid & 31) == 0) { r1[tid >> 5] = s1; r2[tid >> 5] = s2; }
    __syncthreads();
    if (tid == 0) {
        float t1 = 0.f, t2 = 0.f;
        #pragma unroll
        for (int i = 0; i < 8; i++) { t1 += r1[i]; t2 += r2[i]; }
        float mu = t1 / (float)H_;
        mu_s = mu; rs_s = rsqrtf(t2 / (float)H_ - mu * mu + 1e-5f);
    }
    __syncthreads();
    for (int h = tid; h < H_; h += 256) z[h] = (z[h] - mu_s) * rs_s * lng[h] + lnb[h];
    __syncthreads();
    for (int f = tid; f < F_; f += 256) {
        float acc = b1[f];
        for (int h = 0; h < H_; h++) acc += z[h] * W1[(size_t)h * F_ + f];
        a[f] = fmaxf(acc, 0.f);
    }
    __syncthreads();
    for (int h2 = tid; h2 < H_; h2 += 256) {
        float acc = b2[h2];
        for (int f = 0; f < F_; f++) acc += a[f] * W2[(size_t)f * H_ + h2];
        out[b * H_ + h2] = acc;
    }
}

// ---------------------------------------------------------------------------
extern "C" void kernel_launch(void* const* d_in, const int* in_sizes, int n_in,
                              void* d_out, int out_size) {
    const float* x   = (const float*)d_in[0];
    const float* We  = (const float*)d_in[1];
    const float* be  = (const float*)d_in[2];
    const float* Wb  = (const float*)d_in[3];
    const float* A   = (const float*)d_in[4];
    const float* Wr  = (const float*)d_in[5];
    const float* br  = (const float*)d_in[6];
    const float* lng = (const float*)d_in[7];
    const float* lnb = (const float*)d_in[8];
    const float* W1  = (const float*)d_in[9];
    const float* b1  = (const float*)d_in[10];
    const float* W2  = (const float*)d_in[11];
    const float* b2  = (const float*)d_in[12];
    float* out = (float*)d_out;

    bf16 *A0h, *A0l, *Uh, *Ul, *Ph, *Pl;
    float *Gf, *S1;
    cudaGetSymbolAddress((void**)&A0h, g_A0h);
    cudaGetSymbolAddress((void**)&A0l, g_A0l);
    cudaGetSymbolAddress((void**)&Uh,  g_Uh);
    cudaGetSymbolAddress((void**)&Ul,  g_Ul);
    cudaGetSymbolAddress((void**)&Ph,  g_Ph);
    cudaGetSymbolAddress((void**)&Pl,  g_Pl);
    cudaGetSymbolAddress((void**)&Gf,  g_Gf);
    cudaGetSymbolAddress((void**)&S1,  g_S1);

    bf16* P0h = Ph;               bf16* P0l = Pl;                // A^2
    bf16* P1h = Ph + H_ * H_;     bf16* P1l = Pl + H_ * H_;      // A^4
    bf16* P2h = Ph + 2 * H_ * H_; bf16* P2l = Pl + 2 * H_ * H_;  // A^8
    bf16* P3h = Ph + 3 * H_ * H_; bf16* P3l = Pl + 3 * H_ * H_;  // A^16

    // merged prep: splitA + initW0 + gather + barrier init
    k_prep<<<1024 + 260 + 2048, 256>>>(A, We, be, Wb, x);

    // merged doubling + power chain: [U_new ; A^(2s)] = [U_prev ; A^s] @ A^s
    k_tgemm<<<dim3(8, 11), 256>>>(Uh, Ul, A0h, A0l, 130, 642, H_, A0h, A0l,
        Uh + 130 * H_, Ul + 130 * H_, P0h, P0l, nullptr, nullptr, 512, 512);
    k_tgemm<<<dim3(8, 13), 256>>>(Uh, Ul, P0h, P0l, 260, 772, H_, P0h, P0l,
        Uh + 260 * H_, Ul + 260 * H_, P1h, P1l, nullptr, nullptr, 512, 512);
    k_tgemm<<<dim3(8, 17), 256>>>(Uh, Ul, P1h, P1l, 520, 1032, H_, P1h, P1l,
        Uh + 520 * H_, Ul + 520 * H_, P2h, P2l, nullptr, nullptr, 512, 512);
    k_tgemm<<<dim3(8, 25), 256>>>(Uh, Ul, P2h, P2l, 1040, 1552, H_, P2h, P2l,
        Uh + 1040 * H_, Ul + 1040 * H_, P3h, P3l, nullptr, Gf, 512, 512);

    // Z = X @ U' (const rows folded into scan bias), split-K partials
    k_zgemm<<<dim3(8, 4, NSPLIT), 256>>>();

    // single-launch Horner scan over q=15..0
    k_scanall<<<SCAN_BLOCKS, 256>>>();

    // after 16 iters (last i=15, odd) the state is in g_S1
    k_final<<<B_, 256>>>(S1, x, Wr, br, lng, lnb, W1, b1, W2, b2, out);
}

// round 11
// speedup vs baseline: 1.4114x; 1.4114x over previous
#include <cuda_runtime.h>
#include <cuda_bf16.h>
#include <cstdint>

#define B_ 16
#define T_ 2048
#define L_ 128
#define H_ 512
#define HH (H_ * H_)
#define M_IN 256
#define F_ 1024
#define LP 130                 // U table row-block: 128 ch + 1 const + 1 pad
#define C_CHUNK 16
#define KX 2048                // X k-width (no const row)
#define MZ 256                 // 16 q * 16 batch
#define NSPLIT 8
#define KPER 256
#define GRID 144               // persistent blocks, <= 148 SMs (co-resident)

typedef __nv_bfloat16 bf16;

__device__ __align__(16) bf16 g_A0h[HH], g_A0l[HH];
__device__ __align__(16) bf16 g_Uh[C_CHUNK * LP * H_], g_Ul[C_CHUNK * LP * H_];
__device__ __align__(16) bf16 g_Ph[4 * HH], g_Pl[4 * HH];
__device__ __align__(16) bf16 g_Xh[MZ * KX], g_Xl[MZ * KX];
__device__ __align__(16) float g_Gf[HH];
__device__ __align__(16) float g_Zp[NSPLIT * MZ * H_];
__device__ __align__(16) float g_S0[B_ * H_], g_S1[B_ * H_];
__device__ int g_cnt;
__device__ int g_gen;

__device__ __forceinline__ void splitw(float v, bf16* ph, bf16* pl) {
    bf16 h = __float2bfloat16(v);
    *ph = h;
    *pl = __float2bfloat16(v - __bfloat162float(h));
}

// ------------------------- prep: splitA + initW0 + bar reset ---------------
__global__ void k_prep(const float* __restrict__ A, const float* __restrict__ We,
                       const float* __restrict__ be, const float* __restrict__ Wb) {
    const int NB_A = HH / 256;   // 1024
    int bid = blockIdx.x, tid = threadIdx.x;
    if (bid == 0 && tid == 0) { g_cnt = 0; g_gen = 0; }
    if (bid < NB_A) {
        int i = bid * 256 + tid;
        splitw(A[i], &g_A0h[i], &g_A0l[i]);
    } else {
        int i = (bid - NB_A) * 256 + tid;
        if (i >= LP * H_) return;
        int l = i >> 9, h = i & 511;
        float acc = 0.f;
        if (l < 128) { for (int m = 0; m < M_IN; m++) acc += We[l * M_IN + m] * Wb[m * H_ + h]; }
        else if (l == 128) { for (int m = 0; m < M_IN; m++) acc += be[m] * Wb[m * H_ + h]; }
        splitw(acc, &g_Uh[i], &g_Ul[i]);
    }
}

// ---------------------------------------------------------------------------
__device__ __forceinline__ void ldsm4(uint32_t* r, const void* p) {
    uint32_t addr = (uint32_t)__cvta_generic_to_shared(p);
    asm volatile("ldmatrix.sync.aligned.m8n8.x4.shared.b16 {%0,%1,%2,%3}, [%4];"
                 : "=r"(r[0]), "=r"(r[1]), "=r"(r[2]), "=r"(r[3]) : "r"(addr));
}
__device__ __forceinline__ void ldsm4t(uint32_t* r, const void* p) {
    uint32_t addr = (uint32_t)__cvta_generic_to_shared(p);
    asm volatile("ldmatrix.sync.aligned.m8n8.x4.trans.shared.b16 {%0,%1,%2,%3}, [%4];"
                 : "=r"(r[0]), "=r"(r[1]), "=r"(r[2]), "=r"(r[3]) : "r"(addr));
}
__device__ __forceinline__ void mma16816(float* d, const uint32_t* a, const uint32_t* b) {
    asm volatile("mma.sync.aligned.m16n8k16.row.col.f32.bf16.bf16.f32 "
                 "{%0,%1,%2,%3}, {%4,%5,%6,%7}, {%8,%9}, {%0,%1,%2,%3};"
                 : "+f"(d[0]), "+f"(d[1]), "+f"(d[2]), "+f"(d[3])
                 : "r"(a[0]), "r"(a[1]), "r"(a[2]), "r"(a[3]), "r"(b[0]), "r"(b[1]));
}

// grid-wide barrier (all GRID blocks must be resident)
__device__ __forceinline__ void gbar(int& epoch) {
    __syncthreads();
    __threadfence();
    if (threadIdx.x == 0) {
        int t = atomicAdd(&g_cnt, 1);
        if (t == GRID - 1) {
            atomicExch(&g_cnt, 0);
            __threadfence();
            atomicAdd(&g_gen, 1);
        }
        while (*(volatile int*)&g_gen < epoch + 1) {}
    }
    __syncthreads();
    epoch++;
}

// smem carve (bf16 units) for GEMM tiles:
//   ash [2][64][40] @0, asl @5120, bsh [2][32][72] @10240, bsl @14848
#define SMEM_BYTES 38912

// one 64x64 stage tile: C = [U(:Mu) ; A2] @ A2, k=512, double-buffered
__device__ void tg_tile(const bf16* __restrict__ A2h, const bf16* __restrict__ A2l,
                        int Mu, int Mtot,
                        bf16* C1h, bf16* C1l, bf16* C2h, bf16* C2l, float* C2f,
                        int tile, char* sm)
{
    bf16* ash = (bf16*)sm;
    bf16* asl = ash + 5120;
    bf16* bsh = asl + 5120;
    bf16* bsl = bsh + 4608;

    int tid = threadIdx.x;
    int lane = tid & 31, wid = tid >> 5;
    int wm = wid & 1, wn = wid >> 1;
    int row0 = (tile >> 3) * 64, col0 = (tile & 7) * 64;

    float acc[2][2][4];
    #pragma unroll
    for (int a = 0; a < 2; a++)
        #pragma unroll
        for (int b = 0; b < 2; b++)
            #pragma unroll
            for (int c = 0; c < 4; c++) acc[a][b][c] = 0.f;

    int a_r = (lane & 7) + (lane & 8);
    int a_c = (lane & 16) ? 8 : 0;
    int b_r = (lane & 7) + (lane & 8);
    int b_c = (lane & 16) ? 8 : 0;

    int am = tid >> 2, ac8 = (tid & 3) * 8;
    int sbk = tid >> 3, sbn = (tid & 7) * 8;

    int ar_g = row0 + am;
    bool a_ok = (ar_g < Mtot);
    bool a_lo = a_ok && (ar_g < Mu);
    const bf16* ash_src = a_ok ? ((a_lo ? g_Uh : A2h) + (size_t)(a_lo ? ar_g : ar_g - Mu) * H_ + ac8) : nullptr;
    const bf16* asl_src = a_ok ? ((a_lo ? g_Ul : A2l) + (size_t)(a_lo ? ar_g : ar_g - Mu) * H_ + ac8) : nullptr;
    const bf16* bsh_src = A2h + (size_t)sbk * H_ + col0 + sbn;
    const bf16* bsl_src = A2l + (size_t)sbk * H_ + col0 + sbn;

    uint4 pAh = make_uint4(0, 0, 0, 0), pAl = pAh, pBh, pBl;
    if (a_ok) { pAh = *(const uint4*)(ash_src); pAl = *(const uint4*)(asl_src); }
    pBh = *(const uint4*)(bsh_src);
    pBl = *(const uint4*)(bsl_src);

    int st = 0;
    #pragma unroll 1
    for (int it = 0; it < 16; it++) {
        *(uint4*)&ash[st * 2560 + am * 40 + ac8] = pAh;
        *(uint4*)&asl[st * 2560 + am * 40 + ac8] = pAl;
        *(uint4*)&bsh[st * 2304 + sbk * 72 + sbn] = pBh;
        *(uint4*)&bsl[st * 2304 + sbk * 72 + sbn] = pBl;
        __syncthreads();

        if (it + 1 < 16) {
            int kn = (it + 1) << 5;
            if (a_ok) { pAh = *(const uint4*)(ash_src + kn); pAl = *(const uint4*)(asl_src + kn); }
            pBh = *(const uint4*)(bsh_src + (size_t)kn * H_);
            pBl = *(const uint4*)(bsl_src + (size_t)kn * H_);
        }

        #pragma unroll
        for (int ks = 0; ks < 2; ks++) {
            int kc = ks * 16;
            uint32_t ah[2][4], al[2][4], bh[4], bl[4];
            #pragma unroll
            for (int mt = 0; mt < 2; mt++) {
                int mr = wm * 32 + mt * 16 + a_r;
                ldsm4(ah[mt], &ash[st * 2560 + mr * 40 + kc + a_c]);
                ldsm4(al[mt], &asl[st * 2560 + mr * 40 + kc + a_c]);
            }
            {
                int nb = wn * 16 + b_c;
                ldsm4t(bh, &bsh[st * 2304 + (kc + b_r) * 72 + nb]);
                ldsm4t(bl, &bsl[st * 2304 + (kc + b_r) * 72 + nb]);
            }
            #pragma unroll
            for (int mt = 0; mt < 2; mt++)
                #pragma unroll
                for (int nt = 0; nt < 2; nt++) {
                    const uint32_t* bhf = &bh[nt * 2];
                    const uint32_t* blf = &bl[nt * 2];
                    mma16816(acc[mt][nt], ah[mt], bhf);
                    mma16816(acc[mt][nt], ah[mt], blf);
                    mma16816(acc[mt][nt], al[mt], bhf);
                }
        }
        st ^= 1;
    }
    __syncthreads();   // protect smem before next tile reuses it

    #pragma unroll
    for (int mt = 0; mt < 2; mt++)
        #pragma unroll
        for (int nt = 0; nt < 2; nt++) {
            int c = col0 + wn * 16 + nt * 8 + (lane & 3) * 2;
            #pragma unroll
            for (int half = 0; half < 2; half++) {
                int r = row0 + wm * 32 + mt * 16 + (lane >> 2) + half * 8;
                if (r >= Mtot) continue;
                float v0 = acc[mt][nt][half * 2], v1 = acc[mt][nt][half * 2 + 1];
                bool lo = (r < Mu);
                size_t ro = lo ? (size_t)r * H_ : (size_t)(r - Mu) * H_;
                bf16* ch = lo ? C1h : C2h;
                bf16* cl = lo ? C1l : C2l;
                splitw(v0, &ch[ro + c], &cl[ro + c]);
                splitw(v1, &ch[ro + c + 1], &cl[ro + c + 1]);
                if (!lo && C2f) { C2f[ro + c] = v0; C2f[ro + c + 1] = v1; }
            }
        }
}

// one 64x64 zgemm tile: Zp[bz] = X @ U' (U' row k = U row (k>>7)*130+(k&127))
__device__ void z_tile(int tile, char* sm) {
    bf16* ash = (bf16*)sm;
    bf16* asl = ash + 5120;
    bf16* bsh = asl + 5120;
    bf16* bsl = bsh + 4608;

    int tid = threadIdx.x;
    int lane = tid & 31, wid = tid >> 5;
    int wm = wid & 1, wn = wid >> 1;
    int bx = tile & 7, by = (tile >> 3) & 3, bz = tile >> 5;
    int row0 = by * 64, col0 = bx * 64;
    int k0 = bz * KPER;
    size_t coff = (size_t)bz * MZ * H_;

    float acc[2][2][4];
    #pragma unroll
    for (int a = 0; a < 2; a++)
        #pragma unroll
        for (int b = 0; b < 2; b++)
            #pragma unroll
            for (int c = 0; c < 4; c++) acc[a][b][c] = 0.f;

    int a_r = (lane & 7) + (lane & 8);
    int a_c = (lane & 16) ? 8 : 0;
    int b_r = (lane & 7) + (lane & 8);
    int b_c = (lane & 16) ? 8 : 0;

    int am = tid >> 2, ac8 = (tid & 3) * 8;
    int sbk = tid >> 3, sbn = (tid & 7) * 8;

    const bf16* ash_src = g_Xh + (size_t)(row0 + am) * KX + ac8;
    const bf16* asl_src = g_Xl + (size_t)(row0 + am) * KX + ac8;

    uint4 pAh, pAl, pBh, pBl;
    {
        pAh = *(const uint4*)(ash_src + k0);
        pAl = *(const uint4*)(asl_src + k0);
        int kg = k0 + sbk;
        size_t brow = (size_t)((kg >> 7) * LP + (kg & 127)) * H_ + col0 + sbn;
        pBh = *(const uint4*)(g_Uh + brow);
        pBl = *(const uint4*)(g_Ul + brow);
    }

    int st = 0;
    #pragma unroll 1
    for (int it = 0; it < (KPER >> 5); it++) {
        *(uint4*)&ash[st * 2560 + am * 40 + ac8] = pAh;
        *(uint4*)&asl[st * 2560 + am * 40 + ac8] = pAl;
        *(uint4*)&bsh[st * 2304 + sbk * 72 + sbn] = pBh;
        *(uint4*)&bsl[st * 2304 + sbk * 72 + sbn] = pBl;
        __syncthreads();

        if (it + 1 < (KPER >> 5)) {
            int kn = k0 + ((it + 1) << 5);
            pAh = *(const uint4*)(ash_src + kn);
            pAl = *(const uint4*)(asl_src + kn);
            int kg = kn + sbk;
            size_t brow = (size_t)((kg >> 7) * LP + (kg & 127)) * H_ + col0 + sbn;
            pBh = *(const uint4*)(g_Uh + brow);
            pBl = *(const uint4*)(g_Ul + brow);
        }

        #pragma unroll
        for (int ks = 0; ks < 2; ks++) {
            int kc = ks * 16;
            uint32_t ah[2][4], al[2][4], bh[4], bl[4];
            #pragma unroll
            for (int mt = 0; mt < 2; mt++) {
                int mr = wm * 32 + mt * 16 + a_r;
                ldsm4(ah[mt], &ash[st * 2560 + mr * 40 + kc + a_c]);
                ldsm4(al[mt], &asl[st * 2560 + mr * 40 + kc + a_c]);
            }
            {
                int nb = wn * 16 + b_c;
                ldsm4t(bh, &bsh[st * 2304 + (kc + b_r) * 72 + nb]);
                ldsm4t(bl, &bsl[st * 2304 + (kc + b_r) * 72 + nb]);
            }
            #pragma unroll
            for (int mt = 0; mt < 2; mt++)
                #pragma unroll
                for (int nt = 0; nt < 2; nt++) {
                    const uint32_t* bhf = &bh[nt * 2];
                    const uint32_t* blf = &bl[nt * 2];
                    mma16816(acc[mt][nt], ah[mt], bhf);
                    mma16816(acc[mt][nt], ah[mt], blf);
                    mma16816(acc[mt][nt], al[mt], bhf);
                }
        }
        st ^= 1;
    }
    __syncthreads();

    #pragma unroll
    for (int mt = 0; mt < 2; mt++)
        #pragma unroll
        for (int nt = 0; nt < 2; nt++) {
            int c = col0 + wn * 16 + nt * 8 + (lane & 3) * 2;
            #pragma unroll
            for (int half = 0; half < 2; half++) {
                int r = row0 + wm * 32 + mt * 16 + (lane >> 2) + half * 8;
                float* cp = g_Zp + coff + (size_t)r * H_ + c;
                cp[0] = acc[mt][nt][half * 2];
                cp[1] = acc[mt][nt][half * 2 + 1];
            }
        }
}

// ------------------------------- mega kernel -------------------------------
__global__ __launch_bounds__(256) void k_mega(
    const float* __restrict__ x,
    const float* __restrict__ Wr, const float* __restrict__ br,
    const float* __restrict__ lng, const float* __restrict__ lnb,
    const float* __restrict__ W1, const float* __restrict__ b1,
    const float* __restrict__ W2, const float* __restrict__ b2,
    float* __restrict__ out)
{
    __shared__ __align__(16) char sm[SMEM_BYTES];
    int bid = blockIdx.x, tid = threadIdx.x;
    int epoch = 0;

    // ---- phase 0: gather X (strided over all blocks) + stage 0 ----
    for (int i = bid * 256 + tid; i < MZ * KX; i += GRID * 256) {
        int m = i >> 11, kk = i & 2047;
        int r = kk >> 7, l = kk & 127;
        int q = m >> 4, b = m & 15;
        float v = x[((size_t)b * T_ + (T_ - 1) - (q * C_CHUNK + r)) * L_ + l];
        splitw(v, &g_Xh[i], &g_Xl[i]);
    }
    {
        const int MuT[4] = {130, 260, 520, 1040};
        const int NTT[4] = {88, 104, 136, 200};   // ceil(Mtot/64)*8
        for (int s = 0; s < 4; s++) {
            const bf16* A2h = s ? g_Ph + (size_t)(s - 1) * HH : g_A0h;
            const bf16* A2l = s ? g_Pl + (size_t)(s - 1) * HH : g_A0l;
            int Mu = MuT[s];
            for (int t = bid; t < NTT[s]; t += GRID)
                tg_tile(A2h, A2l, Mu, Mu + H_,
                        g_Uh + (size_t)Mu * H_, g_Ul + (size_t)Mu * H_,
                        g_Ph + (size_t)s * HH, g_Pl + (size_t)s * HH,
                        (s == 3) ? g_Gf : nullptr, t, sm);
            gbar(epoch);
        }
    }

    // ---- phase 4: zgemm (256 tiles) ----
    for (int t = bid; t < 8 * 4 * NSPLIT; t += GRID) z_tile(t, sm);
    gbar(epoch);

    // ---- phase 5: Horner scan (bid < 64 compute; all blocks join barriers) ----
    {
        float* Ssm  = (float*)sm;        // [4][512]
        float* red  = Ssm + 2048;        // [32][128]
        float* bias = red + 4096;        // [32]
        bool sblk = (bid < 64);
        int bg = bid >> 4, hg = bid & 15;
        int krep = tid >> 3, hslot = tid & 7;
        int h = hg * 32 + hslot * 4;
        const float* gp = g_Gf + (size_t)(krep * 16) * H_ + h;

        if (sblk) {
            if (tid < 32) {
                int hc = hg * 32 + tid;
                float s = 0.f;
                #pragma unroll
                for (int r = 0; r < C_CHUNK; r++) {
                    size_t off = (size_t)(r * LP + 128) * H_ + hc;
                    s += __bfloat162float(g_Uh[off]) + __bfloat162float(g_Ul[off]);
                }
                bias[tid] = s;
            }
            __syncthreads();
        }

        for (int i = 0; i < 16; i++) {
            if (sblk) {
                int q = 15 - i;
                float a0[4] = {}, a1[4] = {}, a2[4] = {}, a3[4] = {};
                if (i > 0) {
                    const float* Sin = ((i - 1) & 1) ? g_S1 : g_S0;
                    for (int t = tid; t < 4 * H_; t += 256)
                        Ssm[(t >> 9) * H_ + (t & 511)] = Sin[(bg * 4 + (t >> 9)) * H_ + (t & 511)];
                    __syncthreads();
                    #pragma unroll 4
                    for (int kk = 0; kk < 16; kk++) {
                        int k = (kk + krep) & 15;
                        float4 g = *(const float4*)(gp + (size_t)k * H_);
                        float s0 = Ssm[0 * H_ + krep * 16 + k];
                        float s1 = Ssm[1 * H_ + krep * 16 + k];
                        float s2 = Ssm[2 * H_ + krep * 16 + k];
                        float s3 = Ssm[3 * H_ + krep * 16 + k];
                        a0[0] += s0 * g.x; a0[1] += s0 * g.y; a0[2] += s0 * g.z; a0[3] += s0 * g.w;
                        a1[0] += s1 * g.x; a1[1] += s1 * g.y; a1[2] += s1 * g.z; a1[3] += s1 * g.w;
                        a2[0] += s2 * g.x; a2[1] += s2 * g.y; a2[2] += s2 * g.z; a2[3] += s2 * g.w;
                        a3[0] += s3 * g.x; a3[1] += s3 * g.y; a3[2] += s3 * g.z; a3[3] += s3 * g.w;
                    }
                }
                *(float4*)&red[krep * 128 + 0 * 32 + hslot * 4] = *(float4*)a0;
                *(float4*)&red[krep * 128 + 1 * 32 + hslot * 4] = *(float4*)a1;
                *(float4*)&red[krep * 128 + 2 * 32 + hslot * 4] = *(float4*)a2;
                *(float4*)&red[krep * 128 + 3 * 32 + hslot * 4] = *(float4*)a3;
                __syncthreads();
                if (tid < 128) {
                    float v = 0.f;
                    #pragma unroll
                    for (int s = 0; s < 32; s++) v += red[s * 128 + tid];
                    int b = tid >> 5, hcl = tid & 31;
                    int m = q * 16 + bg * 4 + b;
                    int hc = hg * 32 + hcl;
                    float z = bias[hcl];
                    #pragma unroll
                    for (int s2 = 0; s2 < NSPLIT; s2++)
                        z += g_Zp[(size_t)s2 * (MZ * H_) + (size_t)m * H_ + hc];
                    float* Sout = (i & 1) ? g_S1 : g_S0;
                    Sout[(bg * 4 + b) * H_ + hc] = v + z;
                }
                __syncthreads();
            }
            gbar(epoch);
        }
    }

    // ---- phase 6: final LN + MLP (bid < 16) ----
    if (bid < B_) {
        float* xs = (float*)sm;      // [128]
        float* z  = xs + 128;        // [512]
        float* a  = z + 512;         // [1024]
        float* r1 = a + 1024;        // [8]
        float* r2 = r1 + 8;          // [8]
        float* mus = r2 + 8;         // [2]
        int b = bid;
        if (tid < L_) xs[tid] = x[((size_t)b * T_ + (T_ - 1)) * L_ + tid];
        __syncthreads();
        for (int h = tid; h < H_; h += 256) {
            float acc = g_S1[b * H_ + h] + br[h];
            for (int l = 0; l < L_; l++) acc += xs[l] * Wr[(size_t)l * H_ + h];
            z[h] = acc;
        }
        __syncthreads();
        float s1 = 0.f, s2 = 0.f;
        for (int h = tid; h < H_; h += 256) { float v = z[h]; s1 += v; s2 += v * v; }
        #pragma unroll
        for (int o = 16; o; o >>= 1) {
            s1 += __shfl_xor_sync(0xFFFFFFFFu, s1, o);
            s2 += __shfl_xor_sync(0xFFFFFFFFu, s2, o);
        }
        if ((tid & 31) == 0) { r1[tid >> 5] = s1; r2[tid >> 5] = s2; }
        __syncthreads();
        if (tid == 0) {
            float t1 = 0.f, t2 = 0.f;
            #pragma unroll
            for (int i = 0; i < 8; i++) { t1 += r1[i]; t2 += r2[i]; }
            float mu = t1 / (float)H_;
            mus[0] = mu;
            mus[1] = rsqrtf(t2 / (float)H_ - mu * mu + 1e-5f);
        }
        __syncthreads();
        for (int h = tid; h < H_; h += 256) z[h] = (z[h] - mus[0]) * mus[1] * lng[h] + lnb[h];
        __syncthreads();
        for (int f = tid; f < F_; f += 256) {
            float acc = b1[f];
            for (int h = 0; h < H_; h++) acc += z[h] * W1[(size_t)h * F_ + f];
            a[f] = fmaxf(acc, 0.f);
        }
        __syncthreads();
        for (int h2 = tid; h2 < H_; h2 += 256) {
            float acc = b2[h2];
            for (int f = 0; f < F_; f++) acc += a[f] * W2[(size_t)f * H_ + h2];
            out[b * H_ + h2] = acc;
        }
    }
}

// ---------------------------------------------------------------------------
extern "C" void kernel_launch(void* const* d_in, const int* in_sizes, int n_in,
                              void* d_out, int out_size) {
    const float* x   = (const float*)d_in[0];
    const float* We  = (const float*)d_in[1];
    const float* be  = (const float*)d_in[2];
    const float* Wb  = (const float*)d_in[3];
    const float* A   = (const float*)d_in[4];
    const float* Wr  = (const float*)d_in[5];
    const float* br  = (const float*)d_in[6];
    const float* lng = (const float*)d_in[7];
    const float* lnb = (const float*)d_in[8];
    const float* W1  = (const float*)d_in[9];
    const float* b1  = (const float*)d_in[10];
    const float* W2  = (const float*)d_in[11];
    const float* b2  = (const float*)d_in[12];
    float* out = (float*)d_out;

    k_prep<<<1024 + 260, 256>>>(A, We, be, Wb);
    k_mega<<<GRID, 256>>>(x, Wr, br, lng, lnb, W1, b1, W2, b2, out);
}

// round 12
// speedup vs baseline: 1.4332x; 1.0154x over previous
#include <cuda_runtime.h>
#include <cuda_bf16.h>
#include <cstdint>

#define B_ 16
#define T_ 2048
#define L_ 128
#define H_ 512
#define HH (H_ * H_)
#define M_IN 256
#define F_ 1024
#define LP 130                 // U table row-block: 128 ch + 1 const + 1 pad
#define C_CHUNK 16
#define KX 2048                // X k-width (no const row)
#define MZ 256                 // 16 q * 16 batch
#define NSPLIT 8
#define KPER 256
#define GRID 288               // persistent blocks, 2/SM co-resident (<=296)

typedef __nv_bfloat16 bf16;

__device__ __align__(16) bf16 g_A0h[HH], g_A0l[HH];
__device__ __align__(16) bf16 g_Uh[C_CHUNK * LP * H_], g_Ul[C_CHUNK * LP * H_];
__device__ __align__(16) bf16 g_Ph[4 * HH], g_Pl[4 * HH];
__device__ __align__(16) bf16 g_Xh[MZ * KX], g_Xl[MZ * KX];
__device__ __align__(16) float g_Gf[HH];
__device__ __align__(16) float g_Zp[NSPLIT * MZ * H_];
__device__ __align__(16) float g_S0[B_ * H_], g_S1[B_ * H_];
__device__ int g_cnt;
__device__ int g_gen;

__device__ __forceinline__ void splitw(float v, bf16* ph, bf16* pl) {
    bf16 h = __float2bfloat16(v);
    *ph = h;
    *pl = __float2bfloat16(v - __bfloat162float(h));
}

// ------------------------- prep: splitA + initW0 + bar reset ---------------
__global__ void k_prep(const float* __restrict__ A, const float* __restrict__ We,
                       const float* __restrict__ be, const float* __restrict__ Wb) {
    const int NB_A = HH / 256;   // 1024
    int bid = blockIdx.x, tid = threadIdx.x;
    if (bid == 0 && tid == 0) { g_cnt = 0; g_gen = 0; }
    if (bid < NB_A) {
        int i = bid * 256 + tid;
        splitw(A[i], &g_A0h[i], &g_A0l[i]);
    } else {
        int i = (bid - NB_A) * 256 + tid;
        if (i >= LP * H_) return;
        int l = i >> 9, h = i & 511;
        float acc = 0.f;
        if (l < 128) { for (int m = 0; m < M_IN; m++) acc += We[l * M_IN + m] * Wb[m * H_ + h]; }
        else if (l == 128) { for (int m = 0; m < M_IN; m++) acc += be[m] * Wb[m * H_ + h]; }
        splitw(acc, &g_Uh[i], &g_Ul[i]);
    }
}

// ---------------------------------------------------------------------------
__device__ __forceinline__ void ldsm4(uint32_t* r, const void* p) {
    uint32_t addr = (uint32_t)__cvta_generic_to_shared(p);
    asm volatile("ldmatrix.sync.aligned.m8n8.x4.shared.b16 {%0,%1,%2,%3}, [%4];"
                 : "=r"(r[0]), "=r"(r[1]), "=r"(r[2]), "=r"(r[3]) : "r"(addr));
}
__device__ __forceinline__ void ldsm4t(uint32_t* r, const void* p) {
    uint32_t addr = (uint32_t)__cvta_generic_to_shared(p);
    asm volatile("ldmatrix.sync.aligned.m8n8.x4.trans.shared.b16 {%0,%1,%2,%3}, [%4];"
                 : "=r"(r[0]), "=r"(r[1]), "=r"(r[2]), "=r"(r[3]) : "r"(addr));
}
__device__ __forceinline__ void mma16816(float* d, const uint32_t* a, const uint32_t* b) {
    asm volatile("mma.sync.aligned.m16n8k16.row.col.f32.bf16.bf16.f32 "
                 "{%0,%1,%2,%3}, {%4,%5,%6,%7}, {%8,%9}, {%0,%1,%2,%3};"
                 : "+f"(d[0]), "+f"(d[1]), "+f"(d[2]), "+f"(d[3])
                 : "r"(a[0]), "r"(a[1]), "r"(a[2]), "r"(a[3]), "r"(b[0]), "r"(b[1]));
}

// grid-wide barrier (all GRID blocks must be resident)
__device__ __forceinline__ void gbar(int& epoch) {
    __syncthreads();
    __threadfence();
    if (threadIdx.x == 0) {
        int t = atomicAdd(&g_cnt, 1);
        if (t == GRID - 1) {
            atomicExch(&g_cnt, 0);
            __threadfence();
            atomicAdd(&g_gen, 1);
        }
        while (*(volatile int*)&g_gen < epoch + 1) {}
    }
    __syncthreads();
    epoch++;
}

// smem carve (bf16 units) for GEMM tiles:
//   ash [2][64][40] @0, asl @5120, bsh [2][32][72] @10240, bsl @14848
#define SMEM_BYTES 38912

// one 64x64 stage tile: C = [U(:Mu) ; A2] @ A2, k=512, double-buffered
__device__ void tg_tile(const bf16* __restrict__ A2h, const bf16* __restrict__ A2l,
                        int Mu, int Mtot,
                        bf16* C1h, bf16* C1l, bf16* C2h, bf16* C2l, float* C2f,
                        int tile, char* sm)
{
    bf16* ash = (bf16*)sm;
    bf16* asl = ash + 5120;
    bf16* bsh = asl + 5120;
    bf16* bsl = bsh + 4608;

    int tid = threadIdx.x;
    int lane = tid & 31, wid = tid >> 5;
    int wm = wid & 1, wn = wid >> 1;
    int row0 = (tile >> 3) * 64, col0 = (tile & 7) * 64;

    float acc[2][2][4];
    #pragma unroll
    for (int a = 0; a < 2; a++)
        #pragma unroll
        for (int b = 0; b < 2; b++)
            #pragma unroll
            for (int c = 0; c < 4; c++) acc[a][b][c] = 0.f;

    int a_r = (lane & 7) + (lane & 8);
    int a_c = (lane & 16) ? 8 : 0;
    int b_r = (lane & 7) + (lane & 8);
    int b_c = (lane & 16) ? 8 : 0;

    int am = tid >> 2, ac8 = (tid & 3) * 8;
    int sbk = tid >> 3, sbn = (tid & 7) * 8;

    int ar_g = row0 + am;
    bool a_ok = (ar_g < Mtot);
    bool a_lo = a_ok && (ar_g < Mu);
    const bf16* ash_src = a_ok ? ((a_lo ? g_Uh : A2h) + (size_t)(a_lo ? ar_g : ar_g - Mu) * H_ + ac8) : nullptr;
    const bf16* asl_src = a_ok ? ((a_lo ? g_Ul : A2l) + (size_t)(a_lo ? ar_g : ar_g - Mu) * H_ + ac8) : nullptr;
    const bf16* bsh_src = A2h + (size_t)sbk * H_ + col0 + sbn;
    const bf16* bsl_src = A2l + (size_t)sbk * H_ + col0 + sbn;

    uint4 pAh = make_uint4(0, 0, 0, 0), pAl = pAh, pBh, pBl;
    if (a_ok) { pAh = *(const uint4*)(ash_src); pAl = *(const uint4*)(asl_src); }
    pBh = *(const uint4*)(bsh_src);
    pBl = *(const uint4*)(bsl_src);

    int st = 0;
    #pragma unroll 1
    for (int it = 0; it < 16; it++) {
        *(uint4*)&ash[st * 2560 + am * 40 + ac8] = pAh;
        *(uint4*)&asl[st * 2560 + am * 40 + ac8] = pAl;
        *(uint4*)&bsh[st * 2304 + sbk * 72 + sbn] = pBh;
        *(uint4*)&bsl[st * 2304 + sbk * 72 + sbn] = pBl;
        __syncthreads();

        if (it + 1 < 16) {
            int kn = (it + 1) << 5;
            if (a_ok) { pAh = *(const uint4*)(ash_src + kn); pAl = *(const uint4*)(asl_src + kn); }
            pBh = *(const uint4*)(bsh_src + (size_t)kn * H_);
            pBl = *(const uint4*)(bsl_src + (size_t)kn * H_);
        }

        #pragma unroll
        for (int ks = 0; ks < 2; ks++) {
            int kc = ks * 16;
            uint32_t ah[2][4], al[2][4], bh[4], bl[4];
            #pragma unroll
            for (int mt = 0; mt < 2; mt++) {
                int mr = wm * 32 + mt * 16 + a_r;
                ldsm4(ah[mt], &ash[st * 2560 + mr * 40 + kc + a_c]);
                ldsm4(al[mt], &asl[st * 2560 + mr * 40 + kc + a_c]);
            }
            {
                int nb = wn * 16 + b_c;
                ldsm4t(bh, &bsh[st * 2304 + (kc + b_r) * 72 + nb]);
                ldsm4t(bl, &bsl[st * 2304 + (kc + b_r) * 72 + nb]);
            }
            #pragma unroll
            for (int mt = 0; mt < 2; mt++)
                #pragma unroll
                for (int nt = 0; nt < 2; nt++) {
                    const uint32_t* bhf = &bh[nt * 2];
                    const uint32_t* blf = &bl[nt * 2];
                    mma16816(acc[mt][nt], ah[mt], bhf);
                    mma16816(acc[mt][nt], ah[mt], blf);
                    mma16816(acc[mt][nt], al[mt], bhf);
                }
        }
        st ^= 1;
    }
    __syncthreads();   // protect smem before next tile reuses it

    #pragma unroll
    for (int mt = 0; mt < 2; mt++)
        #pragma unroll
        for (int nt = 0; nt < 2; nt++) {
            int c = col0 + wn * 16 + nt * 8 + (lane & 3) * 2;
            #pragma unroll
            for (int half = 0; half < 2; half++) {
                int r = row0 + wm * 32 + mt * 16 + (lane >> 2) + half * 8;
                if (r >= Mtot) continue;
                float v0 = acc[mt][nt][half * 2], v1 = acc[mt][nt][half * 2 + 1];
                bool lo = (r < Mu);
                size_t ro = lo ? (size_t)r * H_ : (size_t)(r - Mu) * H_;
                bf16* ch = lo ? C1h : C2h;
                bf16* cl = lo ? C1l : C2l;
                splitw(v0, &ch[ro + c], &cl[ro + c]);
                splitw(v1, &ch[ro + c + 1], &cl[ro + c + 1]);
                if (!lo && C2f) { C2f[ro + c] = v0; C2f[ro + c + 1] = v1; }
            }
        }
}

// one 64x64 zgemm tile: Zp[bz] = X @ U' (U' row k = U row (k>>7)*130+(k&127))
__device__ void z_tile(int tile, char* sm) {
    bf16* ash = (bf16*)sm;
    bf16* asl = ash + 5120;
    bf16* bsh = asl + 5120;
    bf16* bsl = bsh + 4608;

    int tid = threadIdx.x;
    int lane = tid & 31, wid = tid >> 5;
    int wm = wid & 1, wn = wid >> 1;
    int bx = tile & 7, by = (tile >> 3) & 3, bz = tile >> 5;
    int row0 = by * 64, col0 = bx * 64;
    int k0 = bz * KPER;
    size_t coff = (size_t)bz * MZ * H_;

    float acc[2][2][4];
    #pragma unroll
    for (int a = 0; a < 2; a++)
        #pragma unroll
        for (int b = 0; b < 2; b++)
            #pragma unroll
            for (int c = 0; c < 4; c++) acc[a][b][c] = 0.f;

    int a_r = (lane & 7) + (lane & 8);
    int a_c = (lane & 16) ? 8 : 0;
    int b_r = (lane & 7) + (lane & 8);
    int b_c = (lane & 16) ? 8 : 0;

    int am = tid >> 2, ac8 = (tid & 3) * 8;
    int sbk = tid >> 3, sbn = (tid & 7) * 8;

    const bf16* ash_src = g_Xh + (size_t)(row0 + am) * KX + ac8;
    const bf16* asl_src = g_Xl + (size_t)(row0 + am) * KX + ac8;

    uint4 pAh, pAl, pBh, pBl;
    {
        pAh = *(const uint4*)(ash_src + k0);
        pAl = *(const uint4*)(asl_src + k0);
        int kg = k0 + sbk;
        size_t brow = (size_t)((kg >> 7) * LP + (kg & 127)) * H_ + col0 + sbn;
        pBh = *(const uint4*)(g_Uh + brow);
        pBl = *(const uint4*)(g_Ul + brow);
    }

    int st = 0;
    #pragma unroll 1
    for (int it = 0; it < (KPER >> 5); it++) {
        *(uint4*)&ash[st * 2560 + am * 40 + ac8] = pAh;
        *(uint4*)&asl[st * 2560 + am * 40 + ac8] = pAl;
        *(uint4*)&bsh[st * 2304 + sbk * 72 + sbn] = pBh;
        *(uint4*)&bsl[st * 2304 + sbk * 72 + sbn] = pBl;
        __syncthreads();

        if (it + 1 < (KPER >> 5)) {
            int kn = k0 + ((it + 1) << 5);
            pAh = *(const uint4*)(ash_src + kn);
            pAl = *(const uint4*)(asl_src + kn);
            int kg = kn + sbk;
            size_t brow = (size_t)((kg >> 7) * LP + (kg & 127)) * H_ + col0 + sbn;
            pBh = *(const uint4*)(g_Uh + brow);
            pBl = *(const uint4*)(g_Ul + brow);
        }

        #pragma unroll
        for (int ks = 0; ks < 2; ks++) {
            int kc = ks * 16;
            uint32_t ah[2][4], al[2][4], bh[4], bl[4];
            #pragma unroll
            for (int mt = 0; mt < 2; mt++) {
                int mr = wm * 32 + mt * 16 + a_r;
                ldsm4(ah[mt], &ash[st * 2560 + mr * 40 + kc + a_c]);
                ldsm4(al[mt], &asl[st * 2560 + mr * 40 + kc + a_c]);
            }
            {
                int nb = wn * 16 + b_c;
                ldsm4t(bh, &bsh[st * 2304 + (kc + b_r) * 72 + nb]);
                ldsm4t(bl, &bsl[st * 2304 + (kc + b_r) * 72 + nb]);
            }
            #pragma unroll
            for (int mt = 0; mt < 2; mt++)
                #pragma unroll
                for (int nt = 0; nt < 2; nt++) {
                    const uint32_t* bhf = &bh[nt * 2];
                    const uint32_t* blf = &bl[nt * 2];
                    mma16816(acc[mt][nt], ah[mt], bhf);
                    mma16816(acc[mt][nt], ah[mt], blf);
                    mma16816(acc[mt][nt], al[mt], bhf);
                }
        }
        st ^= 1;
    }
    __syncthreads();

    #pragma unroll
    for (int mt = 0; mt < 2; mt++)
        #pragma unroll
        for (int nt = 0; nt < 2; nt++) {
            int c = col0 + wn * 16 + nt * 8 + (lane & 3) * 2;
            #pragma unroll
            for (int half = 0; half < 2; half++) {
                int r = row0 + wm * 32 + mt * 16 + (lane >> 2) + half * 8;
                float* cp = g_Zp + coff + (size_t)r * H_ + c;
                cp[0] = acc[mt][nt][half * 2];
                cp[1] = acc[mt][nt][half * 2 + 1];
            }
        }
}

// ------------------------------- mega kernel -------------------------------
__global__ __launch_bounds__(256, 2) void k_mega(
    const float* __restrict__ x,
    const float* __restrict__ Wr, const float* __restrict__ br,
    const float* __restrict__ lng, const float* __restrict__ lnb,
    const float* __restrict__ W1, const float* __restrict__ b1,
    const float* __restrict__ W2, const float* __restrict__ b2,
    float* __restrict__ out)
{
    __shared__ __align__(16) char sm[SMEM_BYTES];
    int bid = blockIdx.x, tid = threadIdx.x;
    int epoch = 0;

    // ---- phase 0: gather X (strided over all blocks) + stage 0 ----
    for (int i = bid * 256 + tid; i < MZ * KX; i += GRID * 256) {
        int m = i >> 11, kk = i & 2047;
        int r = kk >> 7, l = kk & 127;
        int q = m >> 4, b = m & 15;
        float v = x[((size_t)b * T_ + (T_ - 1) - (q * C_CHUNK + r)) * L_ + l];
        splitw(v, &g_Xh[i], &g_Xl[i]);
    }
    {
        const int MuT[4] = {130, 260, 520, 1040};
        const int NTT[4] = {88, 104, 136, 200};   // ceil(Mtot/64)*8
        for (int s = 0; s < 4; s++) {
            const bf16* A2h = s ? g_Ph + (size_t)(s - 1) * HH : g_A0h;
            const bf16* A2l = s ? g_Pl + (size_t)(s - 1) * HH : g_A0l;
            int Mu = MuT[s];
            for (int t = bid; t < NTT[s]; t += GRID)
                tg_tile(A2h, A2l, Mu, Mu + H_,
                        g_Uh + (size_t)Mu * H_, g_Ul + (size_t)Mu * H_,
                        g_Ph + (size_t)s * HH, g_Pl + (size_t)s * HH,
                        (s == 3) ? g_Gf : nullptr, t, sm);
            gbar(epoch);
        }
    }

    // ---- phase 4: zgemm (256 tiles) ----
    for (int t = bid; t < 8 * 4 * NSPLIT; t += GRID) z_tile(t, sm);
    gbar(epoch);

    // ---- phase 5: Horner scan (bid < 64 compute; all blocks join barriers) ----
    {
        float* Ssm  = (float*)sm;        // [4][512]
        float* red  = Ssm + 2048;        // [32][128]
        float* bias = red + 4096;        // [32]
        bool sblk = (bid < 64);
        int bg = bid >> 4, hg = bid & 15;
        int krep = tid >> 3, hslot = tid & 7;
        int h = hg * 32 + hslot * 4;
        const float* gp = g_Gf + (size_t)(krep * 16) * H_ + h;

        if (sblk) {
            if (tid < 32) {
                int hc = hg * 32 + tid;
                float s = 0.f;
                #pragma unroll
                for (int r = 0; r < C_CHUNK; r++) {
                    size_t off = (size_t)(r * LP + 128) * H_ + hc;
                    s += __bfloat162float(g_Uh[off]) + __bfloat162float(g_Ul[off]);
                }
                bias[tid] = s;
            }
            __syncthreads();
        }

        for (int i = 0; i < 16; i++) {
            if (sblk) {
                int q = 15 - i;
                float a0[4] = {}, a1[4] = {}, a2[4] = {}, a3[4] = {};
                if (i > 0) {
                    const float* Sin = ((i - 1) & 1) ? g_S1 : g_S0;
                    for (int t = tid; t < 4 * H_; t += 256)
                        Ssm[(t >> 9) * H_ + (t & 511)] = Sin[(bg * 4 + (t >> 9)) * H_ + (t & 511)];
                    __syncthreads();
                    #pragma unroll 4
                    for (int kk = 0; kk < 16; kk++) {
                        int k = (kk + krep) & 15;
                        float4 g = *(const float4*)(gp + (size_t)k * H_);
                        float s0 = Ssm[0 * H_ + krep * 16 + k];
                        float s1 = Ssm[1 * H_ + krep * 16 + k];
                        float s2 = Ssm[2 * H_ + krep * 16 + k];
                        float s3 = Ssm[3 * H_ + krep * 16 + k];
                        a0[0] += s0 * g.x; a0[1] += s0 * g.y; a0[2] += s0 * g.z; a0[3] += s0 * g.w;
                        a1[0] += s1 * g.x; a1[1] += s1 * g.y; a1[2] += s1 * g.z; a1[3] += s1 * g.w;
                        a2[0] += s2 * g.x; a2[1] += s2 * g.y; a2[2] += s2 * g.z; a2[3] += s2 * g.w;
                        a3[0] += s3 * g.x; a3[1] += s3 * g.y; a3[2] += s3 * g.z; a3[3] += s3 * g.w;
                    }
                }
                *(float4*)&red[krep * 128 + 0 * 32 + hslot * 4] = *(float4*)a0;
                *(float4*)&red[krep * 128 + 1 * 32 + hslot * 4] = *(float4*)a1;
                *(float4*)&red[krep * 128 + 2 * 32 + hslot * 4] = *(float4*)a2;
                *(float4*)&red[krep * 128 + 3 * 32 + hslot * 4] = *(float4*)a3;
                __syncthreads();
                if (tid < 128) {
                    float v = 0.f;
                    #pragma unroll
                    for (int s = 0; s < 32; s++) v += red[s * 128 + tid];
                    int b = tid >> 5, hcl = tid & 31;
                    int m = q * 16 + bg * 4 + b;
                    int hc = hg * 32 + hcl;
                    float z = bias[hcl];
                    #pragma unroll
                    for (int s2 = 0; s2 < NSPLIT; s2++)
                        z += g_Zp[(size_t)s2 * (MZ * H_) + (size_t)m * H_ + hc];
                    float* Sout = (i & 1) ? g_S1 : g_S0;
                    Sout[(bg * 4 + b) * H_ + hc] = v + z;
                }
                __syncthreads();
            }
            gbar(epoch);
        }
    }

    // ---- phase 6: final LN + MLP (bid < 16) ----
    if (bid < B_) {
        float* xs = (float*)sm;      // [128]
        float* z  = xs + 128;        // [512]
        float* a  = z + 512;         // [1024]
        float* r1 = a + 1024;        // [8]
        float* r2 = r1 + 8;          // [8]
        float* mus = r2 + 8;         // [2]
        int b = bid;
        if (tid < L_) xs[tid] = x[((size_t)b * T_ + (T_ - 1)) * L_ + tid];
        __syncthreads();
        for (int h = tid; h < H_; h += 256) {
            float acc = g_S1[b * H_ + h] + br[h];
            for (int l = 0; l < L_; l++) acc += xs[l] * Wr[(size_t)l * H_ + h];
            z[h] = acc;
        }
        __syncthreads();
        float s1 = 0.f, s2 = 0.f;
        for (int h = tid; h < H_; h += 256) { float v = z[h]; s1 += v; s2 += v * v; }
        #pragma unroll
        for (int o = 16; o; o >>= 1) {
            s1 += __shfl_xor_sync(0xFFFFFFFFu, s1, o);
            s2 += __shfl_xor_sync(0xFFFFFFFFu, s2, o);
        }
        if ((tid & 31) == 0) { r1[tid >> 5] = s1; r2[tid >> 5] = s2; }
        __syncthreads();
        if (tid == 0) {
            float t1 = 0.f, t2 = 0.f;
            #pragma unroll
            for (int i = 0; i < 8; i++) { t1 += r1[i]; t2 += r2[i]; }
            float mu = t1 / (float)H_;
            mus[0] = mu;
            mus[1] = rsqrtf(t2 / (float)H_ - mu * mu + 1e-5f);
        }
        __syncthreads();
        for (int h = tid; h < H_; h += 256) z[h] = (z[h] - mus[0]) * mus[1] * lng[h] + lnb[h];
        __syncthreads();
        for (int f = tid; f < F_; f += 256) {
            float acc = b1[f];
            for (int h = 0; h < H_; h++) acc += z[h] * W1[(size_t)h * F_ + f];
            a[f] = fmaxf(acc, 0.f);
        }
        __syncthreads();
        for (int h2 = tid; h2 < H_; h2 += 256) {
            float acc = b2[h2];
            for (int f = 0; f < F_; f++) acc += a[f] * W2[(size_t)f * H_ + h2];
            out[b * H_ + h2] = acc;
        }
    }
}

// ---------------------------------------------------------------------------
extern "C" void kernel_launch(void* const* d_in, const int* in_sizes, int n_in,
                              void* d_out, int out_size) {
    const float* x   = (const float*)d_in[0];
    const float* We  = (const float*)d_in[1];
    const float* be  = (const float*)d_in[2];
    const float* Wb  = (const float*)d_in[3];
    const float* A   = (const float*)d_in[4];
    const float* Wr  = (const float*)d_in[5];
    const float* br  = (const float*)d_in[6];
    const float* lng = (const float*)d_in[7];
    const float* lnb = (const float*)d_in[8];
    const float* W1  = (const float*)d_in[9];
    const float* b1  = (const float*)d_in[10];
    const float* W2  = (const float*)d_in[11];
    const float* b2  = (const float*)d_in[12];
    float* out = (float*)d_out;

    k_prep<<<1024 + 260, 256>>>(A, We, be, Wb);
    k_mega<<<GRID, 256>>>(x, Wr, br, lng, lnb, W1, b1, W2, b2, out);
}